// round 1
// baseline (speedup 1.0000x reference)
#include <cuda_runtime.h>
#include <cuda_bf16.h>
#include <cstdint>

#define B 8192
#define D 128
#define BI 128
#define BJ 64
#define DKP 132          // padded smem row stride (floats): 16B-aligned, low conflict
#define NCHUNK 9
#define NJT (B / BJ)     // 128 j-tiles
#define NIT (B / BI)     // 64 i-tiles
#define TPB 256

// scratch (no allocs allowed -> device globals)
__device__ float g_sq[B];
__device__ float g_m1[NCHUNK * B];
__device__ float g_m2[NCHUNK * B];
__device__ float g_mn[NCHUNK * B];

__device__ __forceinline__ void fma2(unsigned long long &d,
                                     unsigned long long a,
                                     unsigned long long b) {
    asm("fma.rn.f32x2 %0, %1, %2, %0;" : "+l"(d) : "l"(a), "l"(b));
}

__device__ __forceinline__ float2 unpack2(unsigned long long v) {
    float2 r;
    asm("mov.b64 {%0, %1}, %2;" : "=f"(r.x), "=f"(r.y) : "l"(v));
    return r;
}

// ---------------- row squared norms: one warp per row ----------------
__global__ void sq_kernel(const float* __restrict__ F) {
    int gtid = blockIdx.x * blockDim.x + threadIdx.x;
    int row  = gtid >> 5;
    int lane = gtid & 31;
    float4 v = reinterpret_cast<const float4*>(F)[row * (D / 4) + lane];
    float s = v.x * v.x + v.y * v.y + v.z * v.z + v.w * v.w;
    #pragma unroll
    for (int d = 16; d > 0; d >>= 1) s += __shfl_xor_sync(0xffffffffu, s, d);
    if (lane == 0) g_sq[row] = s;
}

// ---------------- fused GEMM + hard-mining min trackers ----------------
__global__ __launch_bounds__(TPB, 2)
void tile_kernel(const float* __restrict__ F, const int* __restrict__ lab) {
    extern __shared__ float sm[];
    float* As  = sm;                                   // BI * DKP
    float* Bs  = As + BI * DKP;                        // BJ * DKP
    float* ssq = Bs + BJ * DKP;                        // BJ
    int*   slb = reinterpret_cast<int*>(ssq + BJ);     // BJ

    const int tid = threadIdx.x;
    const int tx  = tid & 15;       // col group (16)
    const int ty  = tid >> 4;       // row group (16) -> 8 rows each
    const int i0    = blockIdx.x * BI;
    const int chunk = blockIdx.y;
    const int jt_beg = (chunk * NJT) / NCHUNK;
    const int jt_end = ((chunk + 1) * NJT) / NCHUNK;

    const float4* F4 = reinterpret_cast<const float4*>(F);

    // load A tile [BI][D] (row-major, padded)
    for (int idx = tid; idx < BI * (D / 4); idx += TPB) {
        int row = idx >> 5, kq = idx & 31;
        *reinterpret_cast<float4*>(&As[row * DKP + kq * 4]) =
            F4[(i0 + row) * (D / 4) + kq];
    }

    int li[8];
    #pragma unroll
    for (int r = 0; r < 8; r++) li[r] = lab[i0 + ty * 8 + r];

    const float FINF = __int_as_float(0x7f800000);
    float m1[8], m2[8], mn[8];
    #pragma unroll
    for (int r = 0; r < 8; r++) { m1[r] = FINF; m2[r] = FINF; mn[r] = FINF; }

    for (int jt = jt_beg; jt < jt_end; jt++) {
        const int j0 = jt * BJ;
        __syncthreads();   // protect Bs/ssq/slb from previous iteration readers
        for (int idx = tid; idx < BJ * (D / 4); idx += TPB) {
            int row = idx >> 5, kq = idx & 31;
            *reinterpret_cast<float4*>(&Bs[row * DKP + kq * 4]) =
                F4[(j0 + row) * (D / 4) + kq];
        }
        if (tid < BJ) { ssq[tid] = g_sq[j0 + tid]; slb[tid] = lab[j0 + tid]; }
        __syncthreads();

        // f32x2 accumulators: .lo = even-k partial, .hi = odd-k partial
        unsigned long long acc[8][4];
        #pragma unroll
        for (int r = 0; r < 8; r++)
            #pragma unroll
            for (int c = 0; c < 4; c++) acc[r][c] = 0ull;

        #pragma unroll 2
        for (int k = 0; k < D; k += 4) {
            ulonglong2 a[8], b[4];
            #pragma unroll
            for (int r = 0; r < 8; r++)
                a[r] = *reinterpret_cast<const ulonglong2*>(
                    &As[(ty * 8 + r) * DKP + k]);
            #pragma unroll
            for (int c = 0; c < 4; c++)
                b[c] = *reinterpret_cast<const ulonglong2*>(
                    &Bs[(tx + 16 * c) * DKP + k]);
            #pragma unroll
            for (int r = 0; r < 8; r++)
                #pragma unroll
                for (int c = 0; c < 4; c++) {
                    fma2(acc[r][c], a[r].x, b[c].x);   // k, k+1
                    fma2(acc[r][c], a[r].y, b[c].y);   // k+2, k+3
                }
        }

        // epilogue: t = sq_j - 2*dot  (monotone surrogate of dist)
        #pragma unroll
        for (int c = 0; c < 4; c++) {
            const int jc  = tx + 16 * c;
            const float sqj = ssq[jc];
            const int   lj  = slb[jc];
            #pragma unroll
            for (int r = 0; r < 8; r++) {
                float2 p = unpack2(acc[r][c]);
                float t  = fmaf(-2.0f, p.x + p.y, sqj);
                bool same = (li[r] == lj);
                float ts = same ? t : FINF;
                float tn = same ? FINF : t;
                m2[r] = fminf(m2[r], fmaxf(m1[r], ts));
                m1[r] = fminf(m1[r], ts);
                mn[r] = fminf(mn[r], tn);
            }
        }
    }

    // reduce across the 16 threads (tx) sharing each row: xor widths stay in-group
    #pragma unroll
    for (int d = 1; d < 16; d <<= 1) {
        #pragma unroll
        for (int r = 0; r < 8; r++) {
            float o1 = __shfl_xor_sync(0xffffffffu, m1[r], d);
            float o2 = __shfl_xor_sync(0xffffffffu, m2[r], d);
            float on = __shfl_xor_sync(0xffffffffu, mn[r], d);
            m2[r] = fminf(fminf(m2[r], o2), fmaxf(m1[r], o1));
            m1[r] = fminf(m1[r], o1);
            mn[r] = fminf(mn[r], on);
        }
    }
    if (tx == 0) {
        #pragma unroll
        for (int r = 0; r < 8; r++) {
            int i = i0 + ty * 8 + r;
            g_m1[chunk * B + i] = m1[r];
            g_m2[chunk * B + i] = m2[r];
            g_mn[chunk * B + i] = mn[r];
        }
    }
}

// ---------------- merge chunks + hinge + mean ----------------
__global__ void merge_kernel(float* __restrict__ out) {
    __shared__ float red[1024];
    const int tid = threadIdx.x;
    const float FINF = __int_as_float(0x7f800000);
    float local = 0.f;
    for (int i = tid; i < B; i += 1024) {
        float a1 = FINF, a2 = FINF, nn = FINF;
        #pragma unroll
        for (int c = 0; c < NCHUNK; c++) {
            float b1 = g_m1[c * B + i];
            float b2 = g_m2[c * B + i];
            a2 = fminf(fminf(a2, b2), fmaxf(a1, b1));
            a1 = fminf(a1, b1);
            nn = fminf(nn, g_mn[c * B + i]);
        }
        float sqi = g_sq[i];
        float pos = sqrtf(fmaxf(sqi + a2 + 1e-5f, 0.f));
        float neg = sqrtf(fmaxf(sqi + nn + 1e-5f, 0.f));
        local += fmaxf(1.0f + pos - neg, 0.f);
    }
    red[tid] = local;
    __syncthreads();
    for (int s = 512; s > 0; s >>= 1) {
        if (tid < s) red[tid] += red[tid + s];
        __syncthreads();
    }
    if (tid == 0) out[0] = red[0] * (1.0f / (float)B);
}

extern "C" void kernel_launch(void* const* d_in, const int* in_sizes, int n_in,
                              void* d_out, int out_size) {
    (void)in_sizes; (void)n_in; (void)out_size;
    const float* F   = (const float*)d_in[0];
    const int*   lab = (const int*)d_in[1];
    float*       out = (float*)d_out;

    const int smem = (BI + BJ) * DKP * (int)sizeof(float)
                   + BJ * ((int)sizeof(float) + (int)sizeof(int));
    cudaFuncSetAttribute(tile_kernel,
                         cudaFuncAttributeMaxDynamicSharedMemorySize, smem);

    sq_kernel<<<B / 8, TPB>>>(F);              // 8 warps/block, 1 warp/row
    dim3 grid(NIT, NCHUNK);
    tile_kernel<<<grid, TPB, smem>>>(F, lab);
    merge_kernel<<<1, 1024>>>(out);
}

// round 2
// speedup vs baseline: 1.5856x; 1.5856x over previous
#include <cuda_runtime.h>
#include <cuda_bf16.h>
#include <cstdint>

#define B 8192
#define D 128
#define BT 128            // square tile
#define ASTR 132          // k-major stride (floats) for As
#define BSTR 132          // k-major stride (floats) for Bs
#define NS 33             // partial slots (offsets 0..32)
#define TPB 256
#define FEPS 1e-5f

// scratch (no allocs allowed -> device globals)
__device__ float g_sq[B];
__device__ float g_rm1[NS * B];
__device__ float g_rm2[NS * B];
__device__ float g_rmn[NS * B];
__device__ float g_cm1[NS * B];
__device__ float g_cm2[NS * B];
__device__ float g_cmn[NS * B];
__device__ float g_bsum[64];

__device__ __forceinline__ void fma2(unsigned long long &d,
                                     unsigned long long a,
                                     unsigned long long b) {
    asm("fma.rn.f32x2 %0, %1, %2, %0;" : "+l"(d) : "l"(a), "l"(b));
}
__device__ __forceinline__ unsigned long long dup2(float a) {
    unsigned long long r;
    asm("mov.b64 %0, {%1, %1};" : "=l"(r) : "f"(a));
    return r;
}
__device__ __forceinline__ float2 unpack2(unsigned long long v) {
    float2 r;
    asm("mov.b64 {%0, %1}, %2;" : "=f"(r.x), "=f"(r.y) : "l"(v));
    return r;
}

// ---------------- row squared norms: one warp per row ----------------
__global__ void sq_kernel(const float* __restrict__ F) {
    int gtid = blockIdx.x * blockDim.x + threadIdx.x;
    int row  = gtid >> 5;
    int lane = gtid & 31;
    float4 v = reinterpret_cast<const float4*>(F)[row * (D / 4) + lane];
    float s = v.x * v.x + v.y * v.y + v.z * v.z + v.w * v.w;
    #pragma unroll
    for (int d = 16; d > 0; d >>= 1) s += __shfl_xor_sync(0xffffffffu, s, d);
    if (lane == 0) g_sq[row] = s;
}

// -------- fused symmetric GEMM tile + row/col hard-mining trackers --------
__global__ __launch_bounds__(TPB, 1)
void tile_kernel(const float* __restrict__ F, const int* __restrict__ lab) {
    extern __shared__ float sm[];
    float* As  = sm;                          // [D][ASTR] k-major
    float* Bs  = As + D * ASTR;               // [D][BSTR] k-major
    float* ssq = Bs + D * BSTR;               // [BT]
    int*   slb = reinterpret_cast<int*>(ssq + BT);
    float* scm = reinterpret_cast<float*>(slb + BT);  // [3][16][BT]

    const int tid = threadIdx.x;
    const int tx  = tid & 15;
    const int ty  = tid >> 4;
    const int it  = blockIdx.x;
    const int off = blockIdx.y;
    const float FINF = __int_as_float(0x7f800000);

    // off==32 only valid for it<32 (each unordered block pair once).
    if (off == 32 && it >= 32) {
        if (tid < BT) {
            int i = it * BT + tid;
            g_rm1[32 * B + i] = FINF; g_rm2[32 * B + i] = FINF; g_rmn[32 * B + i] = FINF;
            int j = ((it + 32) & 63) * BT + tid;
            g_cm1[32 * B + j] = FINF; g_cm2[32 * B + j] = FINF; g_cmn[32 * B + j] = FINF;
        }
        return;
    }

    const int jt = (it + off) & 63;
    const int i0 = it * BT, j0 = jt * BT;
    const bool diag = (off == 0);
    const float4* F4 = reinterpret_cast<const float4*>(F);

    // transpose-load tiles to k-major smem (contiguous STS per warp)
    for (int idx = tid; idx < BT * (D / 4); idx += TPB) {
        int col = idx & 127, kq = idx >> 7;
        float4 v = F4[(i0 + col) * (D / 4) + kq];
        As[(4 * kq + 0) * ASTR + col] = v.x;
        As[(4 * kq + 1) * ASTR + col] = v.y;
        As[(4 * kq + 2) * ASTR + col] = v.z;
        As[(4 * kq + 3) * ASTR + col] = v.w;
    }
    for (int idx = tid; idx < BT * (D / 4); idx += TPB) {
        int col = idx & 127, kq = idx >> 7;
        float4 v = F4[(j0 + col) * (D / 4) + kq];
        Bs[(4 * kq + 0) * BSTR + col] = v.x;
        Bs[(4 * kq + 1) * BSTR + col] = v.y;
        Bs[(4 * kq + 2) * BSTR + col] = v.z;
        Bs[(4 * kq + 3) * BSTR + col] = v.w;
    }
    if (tid < BT) { ssq[tid] = g_sq[j0 + tid]; slb[tid] = lab[j0 + tid]; }

    int   li[8];
    float sqa[8];
    #pragma unroll
    for (int r = 0; r < 8; r++) {
        li[r]  = lab[i0 + ty * 8 + r];
        sqa[r] = g_sq[i0 + ty * 8 + r];
    }
    __syncthreads();

    // acc[r][c] holds dots for cols (2tx+32c, 2tx+32c+1) packed in f32x2
    unsigned long long acc[8][4];
    #pragma unroll
    for (int r = 0; r < 8; r++)
        #pragma unroll
        for (int c = 0; c < 4; c++) acc[r][c] = 0ull;

    #pragma unroll 4
    for (int k = 0; k < D; k++) {
        unsigned long long bp[4], ad[8];
        #pragma unroll
        for (int c = 0; c < 4; c++)
            bp[c] = *reinterpret_cast<const unsigned long long*>(
                &Bs[k * BSTR + 2 * tx + 32 * c]);
        #pragma unroll
        for (int r = 0; r < 8; r++)
            ad[r] = dup2(As[k * ASTR + ty * 8 + r]);
        #pragma unroll
        for (int r = 0; r < 8; r++)
            #pragma unroll
            for (int c = 0; c < 4; c++)
                fma2(acc[r][c], ad[r], bp[c]);
    }

    // epilogue: row trackers (t = sq_j - 2 dot) and col trackers (t' = sq_i - 2 dot)
    float m1[8], m2[8], mn[8], c1[8], c2[8], cn[8];
    #pragma unroll
    for (int r = 0; r < 8; r++) { m1[r] = m2[r] = mn[r] = FINF; c1[r] = c2[r] = cn[r] = FINF; }

    #pragma unroll
    for (int c = 0; c < 4; c++) {
        int jj = 2 * tx + 32 * c;
        float sje = ssq[jj], sjo = ssq[jj + 1];
        int   lje = slb[jj], ljo = slb[jj + 1];
        #pragma unroll
        for (int r = 0; r < 8; r++) {
            int ii = ty * 8 + r;
            float2 p = unpack2(acc[r][c]);
            // even col
            {
                bool same = (li[r] == lje);
                bool rk = !diag || (jj >= ii);
                bool ck = !diag || (jj >  ii);
                float t  = fmaf(-2.f, p.x, sje);
                float t2 = fmaf(-2.f, p.x, sqa[r]);
                float ts = (same && rk) ? t : FINF, tn = (!same && rk) ? t : FINF;
                m2[r] = fminf(m2[r], fmaxf(m1[r], ts)); m1[r] = fminf(m1[r], ts);
                mn[r] = fminf(mn[r], tn);
                int ci = 2 * c;
                float ts2 = (same && ck) ? t2 : FINF, tn2 = (!same && ck) ? t2 : FINF;
                c2[ci] = fminf(c2[ci], fmaxf(c1[ci], ts2)); c1[ci] = fminf(c1[ci], ts2);
                cn[ci] = fminf(cn[ci], tn2);
            }
            // odd col
            {
                int jo = jj + 1;
                bool same = (li[r] == ljo);
                bool rk = !diag || (jo >= ii);
                bool ck = !diag || (jo >  ii);
                float t  = fmaf(-2.f, p.y, sjo);
                float t2 = fmaf(-2.f, p.y, sqa[r]);
                float ts = (same && rk) ? t : FINF, tn = (!same && rk) ? t : FINF;
                m2[r] = fminf(m2[r], fmaxf(m1[r], ts)); m1[r] = fminf(m1[r], ts);
                mn[r] = fminf(mn[r], tn);
                int ci = 2 * c + 1;
                float ts2 = (same && ck) ? t2 : FINF, tn2 = (!same && ck) ? t2 : FINF;
                c2[ci] = fminf(c2[ci], fmaxf(c1[ci], ts2)); c1[ci] = fminf(c1[ci], ts2);
                cn[ci] = fminf(cn[ci], tn2);
            }
        }
    }

    // row reduce across tx (16 lanes of the warp's tx group)
    #pragma unroll
    for (int d = 1; d < 16; d <<= 1) {
        #pragma unroll
        for (int r = 0; r < 8; r++) {
            float o1 = __shfl_xor_sync(0xffffffffu, m1[r], d);
            float o2 = __shfl_xor_sync(0xffffffffu, m2[r], d);
            float on = __shfl_xor_sync(0xffffffffu, mn[r], d);
            m2[r] = fminf(fminf(m2[r], o2), fmaxf(m1[r], o1));
            m1[r] = fminf(m1[r], o1);
            mn[r] = fminf(mn[r], on);
        }
    }
    if (tx == 0) {
        #pragma unroll
        for (int r = 0; r < 8; r++) {
            int i = i0 + ty * 8 + r;
            g_rm1[off * B + i] = m1[r];
            g_rm2[off * B + i] = m2[r];
            g_rmn[off * B + i] = mn[r];
        }
    }

    // col reduce across ty (16 groups) via smem
    #pragma unroll
    for (int c = 0; c < 4; c++)
        #pragma unroll
        for (int h = 0; h < 2; h++) {
            int col = 2 * tx + 32 * c + h, ci = 2 * c + h;
            scm[0 * 16 * BT + ty * BT + col] = c1[ci];
            scm[1 * 16 * BT + ty * BT + col] = c2[ci];
            scm[2 * 16 * BT + ty * BT + col] = cn[ci];
        }
    __syncthreads();
    if (tid < BT) {
        float a1 = FINF, a2 = FINF, an = FINF;
        #pragma unroll
        for (int t = 0; t < 16; t++) {
            float b1 = scm[0 * 16 * BT + t * BT + tid];
            float b2 = scm[1 * 16 * BT + t * BT + tid];
            float bn = scm[2 * 16 * BT + t * BT + tid];
            a2 = fminf(fminf(a2, b2), fmaxf(a1, b1));
            a1 = fminf(a1, b1);
            an = fminf(an, bn);
        }
        g_cm1[off * B + j0 + tid] = a1;
        g_cm2[off * B + j0 + tid] = a2;
        g_cmn[off * B + j0 + tid] = an;
    }
}

// ---------------- merge partials + hinge + block sums ----------------
__global__ void merge1_kernel() {
    const int tid = threadIdx.x;
    const int row = blockIdx.x * 128 + tid;
    const float FINF = __int_as_float(0x7f800000);
    __shared__ float red[128];
    float a1 = FINF, a2 = FINF, an = FINF;
    for (int s = 0; s < NS; s++) {
        float b1 = g_rm1[s * B + row], b2 = g_rm2[s * B + row], bn = g_rmn[s * B + row];
        a2 = fminf(fminf(a2, b2), fmaxf(a1, b1)); a1 = fminf(a1, b1); an = fminf(an, bn);
    }
    for (int s = 0; s < NS; s++) {
        float b1 = g_cm1[s * B + row], b2 = g_cm2[s * B + row], bn = g_cmn[s * B + row];
        a2 = fminf(fminf(a2, b2), fmaxf(a1, b1)); a1 = fminf(a1, b1); an = fminf(an, bn);
    }
    float sqi = g_sq[row];
    float pos = sqrtf(fmaxf(sqi + a2 + FEPS, 0.f));
    float neg = sqrtf(fmaxf(sqi + an + FEPS, 0.f));
    red[tid] = fmaxf(1.0f + pos - neg, 0.f);
    __syncthreads();
    for (int s = 64; s > 0; s >>= 1) {
        if (tid < s) red[tid] += red[tid + s];
        __syncthreads();
    }
    if (tid == 0) g_bsum[blockIdx.x] = red[0];
}

__global__ void merge2_kernel(float* __restrict__ out) {
    int tid = threadIdx.x;   // 32 threads
    float s = g_bsum[tid] + g_bsum[tid + 32];
    #pragma unroll
    for (int d = 16; d > 0; d >>= 1) s += __shfl_xor_sync(0xffffffffu, s, d);
    if (tid == 0) out[0] = s * (1.0f / (float)B);
}

extern "C" void kernel_launch(void* const* d_in, const int* in_sizes, int n_in,
                              void* d_out, int out_size) {
    (void)in_sizes; (void)n_in; (void)out_size;
    const float* F   = (const float*)d_in[0];
    const int*   lab = (const int*)d_in[1];
    float*       out = (float*)d_out;

    const int smem = (D * ASTR + D * BSTR + BT + BT + 3 * 16 * BT) * (int)sizeof(float);
    cudaFuncSetAttribute(tile_kernel,
                         cudaFuncAttributeMaxDynamicSharedMemorySize, smem);

    sq_kernel<<<B / 8, TPB>>>(F);
    dim3 grid(64, NS);
    tile_kernel<<<grid, TPB, smem>>>(F, lab);
    merge1_kernel<<<64, 128>>>();
    merge2_kernel<<<1, 32>>>(out);
}

// round 6
// speedup vs baseline: 3.5991x; 2.2699x over previous
#include <cuda_runtime.h>
#include <cuda_bf16.h>
#include <cstdint>

#define B 8192
#define D 128
#define KD 256            // hi|lo concatenated K
#define AST 264           // smem row stride in bf16 (264*2 = 528B, conflict-free ldmatrix)
#define NSL 2             // j-slot split
#define JT_PER 32         // j-tiles per slot
#define TPB 256
#define FEPS 1e-5f

// ---------------- device scratch ----------------
__device__ float          g_sq[B];
__device__ float2         g_sl[B];              // (sq_j, label bits)
__device__ __nv_bfloat16  g_g2[B * KD];         // [hi(128) | lo(128)] per row, 4MB
__device__ float          g_rm1[NSL * B];
__device__ float          g_rm2[NSL * B];
__device__ float          g_rmn[NSL * B];
__device__ float          g_bsum[64];

// smem byte offsets
#define SM_A   0
#define SM_B0  67584
#define SM_B1  135168
#define SM_ST  202752                            // staging float[4][3][128] = 6144B
#define SMEM_TOTAL 208896

__device__ __forceinline__ uint32_t s2u(const void* p) {
    uint32_t a;
    asm("{ .reg .u64 t; cvta.to.shared.u64 t, %1; cvt.u32.u64 %0, t; }" : "=r"(a) : "l"(p));
    return a;
}
__device__ __forceinline__ void cpa16(uint32_t dst, const void* src) {
    asm volatile("cp.async.cg.shared.global [%0], [%1], 16;" :: "r"(dst), "l"(src));
}
#define CP_COMMIT() asm volatile("cp.async.commit_group;" ::: "memory")
#define CP_WAIT0()  asm volatile("cp.async.wait_group 0;" ::: "memory")

__device__ __forceinline__ void ldsm4(uint32_t& r0, uint32_t& r1, uint32_t& r2,
                                      uint32_t& r3, uint32_t a) {
    asm volatile("ldmatrix.sync.aligned.m8n8.x4.shared.b16 {%0,%1,%2,%3}, [%4];"
                 : "=r"(r0), "=r"(r1), "=r"(r2), "=r"(r3) : "r"(a));
}
// B tile is K-major ([n][k] rows) -> NON-trans ldmatrix gives the correct
// b-fragment (pair spans consecutive k). (.trans was the R3/R5 bug.)
__device__ __forceinline__ void ldsm2(uint32_t& r0, uint32_t& r1, uint32_t a) {
    asm volatile("ldmatrix.sync.aligned.m8n8.x2.shared.b16 {%0,%1}, [%2];"
                 : "=r"(r0), "=r"(r1) : "r"(a));
}
__device__ __forceinline__ void mma16816(float* c, const uint32_t* a, const uint32_t* b) {
    asm volatile(
        "mma.sync.aligned.m16n8k16.row.col.f32.bf16.bf16.f32 "
        "{%0,%1,%2,%3}, {%4,%5,%6,%7}, {%8,%9}, {%0,%1,%2,%3};"
        : "+f"(c[0]), "+f"(c[1]), "+f"(c[2]), "+f"(c[3])
        : "r"(a[0]), "r"(a[1]), "r"(a[2]), "r"(a[3]), "r"(b[0]), "r"(b[1]));
}

// ---------------- prepass 1: row norms + (sq,label) ----------------
__global__ void sq_sl_kernel(const float* __restrict__ F, const int* __restrict__ lab) {
    int gtid = blockIdx.x * blockDim.x + threadIdx.x;
    int row  = gtid >> 5, lane = gtid & 31;
    float4 v = reinterpret_cast<const float4*>(F)[row * (D / 4) + lane];
    float s = v.x * v.x + v.y * v.y + v.z * v.z + v.w * v.w;
    #pragma unroll
    for (int d = 16; d > 0; d >>= 1) s += __shfl_xor_sync(0xffffffffu, s, d);
    if (lane == 0) {
        g_sq[row] = s;
        g_sl[row] = make_float2(s, __int_as_float(lab[row]));
    }
}

// ---------------- prepass 2: hi/lo split to K=256 bf16 ----------------
__global__ void prep_kernel(const float* __restrict__ F) {
    int id  = blockIdx.x * blockDim.x + threadIdx.x;   // B*32 threads
    int row = id >> 5, c4 = (id & 31) << 2;
    float4 v = *reinterpret_cast<const float4*>(F + row * D + c4);
    float vv[4] = {v.x, v.y, v.z, v.w};
    unsigned short h[4], l[4];
    #pragma unroll
    for (int e = 0; e < 4; e++) {
        __nv_bfloat16 bh = __float2bfloat16(vv[e]);
        __nv_bfloat16 bl = __float2bfloat16(vv[e] - __bfloat162float(bh));
        h[e] = __bfloat16_as_ushort(bh);
        l[e] = __bfloat16_as_ushort(bl);
    }
    uint2* dst = reinterpret_cast<uint2*>(g_g2 + row * KD);
    dst[c4 >> 2]        = make_uint2((uint32_t)h[0] | ((uint32_t)h[1] << 16),
                                     (uint32_t)h[2] | ((uint32_t)h[3] << 16));
    dst[(c4 >> 2) + 32] = make_uint2((uint32_t)l[0] | ((uint32_t)l[1] << 16),
                                     (uint32_t)l[2] | ((uint32_t)l[3] << 16));
}

// issue a 128-row x 256-col bf16 tile copy (gmem row r0) into smem at byte off
__device__ __forceinline__ void issue_tile(uint32_t smb, int dst_off, int r0, int tid) {
    #pragma unroll
    for (int p = 0; p < 16; p++) {
        int c   = p * TPB + tid;                 // 0..4095 chunk id (16B chunks)
        int row = c >> 5, off = c & 31;
        cpa16(smb + dst_off + row * (AST * 2) + off * 16,
              g_g2 + (r0 + row) * KD + off * 8);
    }
}

// ---------------- main HMMA + hard-mining kernel ----------------
__global__ __launch_bounds__(TPB)
void hmma_kernel(const int* __restrict__ lab) {
    extern __shared__ char smem[];
    const uint32_t smb = s2u(smem);
    const int tid  = threadIdx.x;
    const int wid  = tid >> 5, lane = tid & 31;
    const int wm   = wid >> 2, wn = wid & 3;     // warp grid 2x4, tile 64x32
    const int q    = lane >> 2, tq = lane & 3;
    const int it   = blockIdx.x, slot = blockIdx.y;
    const int i0   = it * 128;
    const float FINF = __int_as_float(0x7f800000);

    // prologue: A tile + B tile 0
    issue_tile(smb, SM_A, i0, tid);
    issue_tile(smb, SM_B0, (slot * JT_PER) * 128, tid);
    CP_COMMIT();

    // per-thread ldmatrix address row-parts
    const int lrow = lane & 7, grp = lane >> 3;
    int arow[4], brow[4];
    #pragma unroll
    for (int mt = 0; mt < 4; mt++)
        arow[mt] = (wm * 64 + mt * 16 + lrow + (grp & 1) * 8) * AST;
    const int acol = (grp >> 1) * 8;
    #pragma unroll
    for (int nt = 0; nt < 4; nt++)
        brow[nt] = (wn * 32 + nt * 8 + lrow) * AST;
    const int bcol = (grp & 1) * 8;

    int li[4][2];
    #pragma unroll
    for (int mt = 0; mt < 4; mt++) {
        li[mt][0] = lab[i0 + wm * 64 + mt * 16 + q];
        li[mt][1] = lab[i0 + wm * 64 + mt * 16 + q + 8];
    }

    float m1[8], m2[8], mn[8];
    #pragma unroll
    for (int r = 0; r < 8; r++) { m1[r] = FINF; m2[r] = FINF; mn[r] = FINF; }

    CP_WAIT0();
    __syncthreads();

    for (int s = 0; s < JT_PER; s++) {
        const int bufo = (s & 1) ? SM_B1 : SM_B0;
        if (s + 1 < JT_PER) {
            issue_tile(smb, (s & 1) ? SM_B0 : SM_B1,
                       (slot * JT_PER + s + 1) * 128, tid);
            CP_COMMIT();
        }

        float acc[4][4][4];
        #pragma unroll
        for (int mt = 0; mt < 4; mt++)
            #pragma unroll
            for (int nt = 0; nt < 4; nt++)
                #pragma unroll
                for (int e = 0; e < 4; e++) acc[mt][nt][e] = 0.f;

        #pragma unroll
        for (int ks = 0; ks < KD / 16; ks++) {
            const int k0 = ks * 16;
            uint32_t a[4][4], b[4][2];
            #pragma unroll
            for (int mt = 0; mt < 4; mt++)
                ldsm4(a[mt][0], a[mt][1], a[mt][2], a[mt][3],
                      smb + SM_A + (arow[mt] + k0 + acol) * 2);
            #pragma unroll
            for (int nt = 0; nt < 4; nt++)
                ldsm2(b[nt][0], b[nt][1],
                      smb + bufo + (brow[nt] + k0 + bcol) * 2);
            #pragma unroll
            for (int mt = 0; mt < 4; mt++)
                #pragma unroll
                for (int nt = 0; nt < 4; nt++)
                    mma16816(acc[mt][nt], a[mt], b[nt]);
        }

        // epilogue on register accumulators
        const int j0 = (slot * JT_PER + s) * 128;
        #pragma unroll
        for (int nt = 0; nt < 4; nt++) {
            const int c0 = j0 + wn * 32 + nt * 8 + 2 * tq;
            float2 sl0 = g_sl[c0], sl1 = g_sl[c0 + 1];
            const int lj0 = __float_as_int(sl0.y), lj1 = __float_as_int(sl1.y);
            #pragma unroll
            for (int mt = 0; mt < 4; mt++) {
                #pragma unroll
                for (int h = 0; h < 2; h++) {
                    const int r = mt * 2 + h;
                    const int lir = li[mt][h];
                    float t0 = fmaf(-2.f, acc[mt][nt][2 * h],     sl0.x);
                    float t1 = fmaf(-2.f, acc[mt][nt][2 * h + 1], sl1.x);
                    bool s0 = (lir == lj0), s1 = (lir == lj1);
                    float ts = s0 ? t0 : FINF, tn = s0 ? FINF : t0;
                    m2[r] = fminf(m2[r], fmaxf(m1[r], ts));
                    m1[r] = fminf(m1[r], ts);
                    mn[r] = fminf(mn[r], tn);
                    ts = s1 ? t1 : FINF; tn = s1 ? FINF : t1;
                    m2[r] = fminf(m2[r], fmaxf(m1[r], ts));
                    m1[r] = fminf(m1[r], ts);
                    mn[r] = fminf(mn[r], tn);
                }
            }
        }

        if (s + 1 < JT_PER) CP_WAIT0();
        __syncthreads();
    }

    // quad reduce (lanes sharing rows: xor over tq bits)
    #pragma unroll
    for (int d = 1; d < 4; d <<= 1) {
        #pragma unroll
        for (int r = 0; r < 8; r++) {
            float o1 = __shfl_xor_sync(0xffffffffu, m1[r], d);
            float o2 = __shfl_xor_sync(0xffffffffu, m2[r], d);
            float on = __shfl_xor_sync(0xffffffffu, mn[r], d);
            m2[r] = fminf(fminf(m2[r], o2), fmaxf(m1[r], o1));
            m1[r] = fminf(m1[r], o1);
            mn[r] = fminf(mn[r], on);
        }
    }
    float* st = reinterpret_cast<float*>(smem + SM_ST);   // [4][3][128]
    if (tq == 0) {
        #pragma unroll
        for (int mt = 0; mt < 4; mt++)
            #pragma unroll
            for (int h = 0; h < 2; h++) {
                int r = wm * 64 + mt * 16 + q + 8 * h;
                st[wn * 384 + 0 * 128 + r] = m1[mt * 2 + h];
                st[wn * 384 + 1 * 128 + r] = m2[mt * 2 + h];
                st[wn * 384 + 2 * 128 + r] = mn[mt * 2 + h];
            }
    }
    __syncthreads();
    if (tid < 128) {
        float a1 = FINF, a2 = FINF, an = FINF;
        #pragma unroll
        for (int w = 0; w < 4; w++) {
            float b1 = st[w * 384 + tid], b2 = st[w * 384 + 128 + tid],
                  bn = st[w * 384 + 256 + tid];
            a2 = fminf(fminf(a2, b2), fmaxf(a1, b1));
            a1 = fminf(a1, b1);
            an = fminf(an, bn);
        }
        g_rm1[slot * B + i0 + tid] = a1;
        g_rm2[slot * B + i0 + tid] = a2;
        g_rmn[slot * B + i0 + tid] = an;
    }
}

// ---------------- merge partials + hinge + block sums ----------------
__global__ void merge1_kernel() {
    const int tid = threadIdx.x;
    const int row = blockIdx.x * 128 + tid;
    const float FINF = __int_as_float(0x7f800000);
    __shared__ float red[128];
    float a1 = FINF, a2 = FINF, an = FINF;
    #pragma unroll
    for (int s = 0; s < NSL; s++) {
        float b1 = g_rm1[s * B + row], b2 = g_rm2[s * B + row], bn = g_rmn[s * B + row];
        a2 = fminf(fminf(a2, b2), fmaxf(a1, b1));
        a1 = fminf(a1, b1);
        an = fminf(an, bn);
    }
    float sqi = g_sq[row];
    float pos = sqrtf(fmaxf(sqi + a2 + FEPS, 0.f));
    float neg = sqrtf(fmaxf(sqi + an + FEPS, 0.f));
    red[tid] = fmaxf(1.0f + pos - neg, 0.f);
    __syncthreads();
    for (int s = 64; s > 0; s >>= 1) {
        if (tid < s) red[tid] += red[tid + s];
        __syncthreads();
    }
    if (tid == 0) g_bsum[blockIdx.x] = red[0];
}

__global__ void merge2_kernel(float* __restrict__ out) {
    int tid = threadIdx.x;   // 32
    float s = g_bsum[tid] + g_bsum[tid + 32];
    #pragma unroll
    for (int d = 16; d > 0; d >>= 1) s += __shfl_xor_sync(0xffffffffu, s, d);
    if (tid == 0) out[0] = s * (1.0f / (float)B);
}

extern "C" void kernel_launch(void* const* d_in, const int* in_sizes, int n_in,
                              void* d_out, int out_size) {
    (void)in_sizes; (void)n_in; (void)out_size;
    const float* F   = (const float*)d_in[0];
    const int*   lab = (const int*)d_in[1];
    float*       out = (float*)d_out;

    cudaFuncSetAttribute(hmma_kernel,
                         cudaFuncAttributeMaxDynamicSharedMemorySize, SMEM_TOTAL);

    sq_sl_kernel<<<B / 8, TPB>>>(F, lab);
    prep_kernel<<<B * 32 / TPB, TPB>>>(F);
    dim3 grid(64, NSL);
    hmma_kernel<<<grid, NSL == 2 ? dim3(TPB).x : TPB, SMEM_TOTAL>>>(lab);
    merge1_kernel<<<64, 128>>>();
    merge2_kernel<<<1, 32>>>(out);
}